// round 3
// baseline (speedup 1.0000x reference)
#include <cuda_runtime.h>
#include <math.h>

// Problem constants
#define BSZ  256
#define NN   1024
#define TT   100
#define NBLK 128
#define NTHR 128
#define TM   32
#define TN   64
#define KC   32
#define NCH  (NN / KC)

// Output layout (floats)
#define O_ACT 0
#define O_E3H 512
#define O_E5H (512 + 102400)
#define O_C1H (512 + 2*102400)
#define O_E3F (512 + 3*102400)
#define O_E5F (O_E3F + 262144)
#define O_C1F (O_E5F + 262144)

// Persistent device state
__device__ float g_ec3[BSZ*NN];
__device__ float g_ec5[BSZ*NN];
__device__ float g_ca1[BSZ*NN];
__device__ float g_ca3[TT*NN];
__device__ float g_drive[TT*NN];
__device__ unsigned g_arrive = 0;

__device__ __forceinline__ float sigm(float x) {
    return __fdividef(1.0f, 1.0f + __expf(-x));
}

// packed f32x2 FMA: two independent IEEE fp32 fmas per instruction (FFMA2)
#define FFMA2(acc, a2, b2) \
    asm("fma.rn.f32x2 %0, %1, %2, %0;" : "+l"(acc) : "l"(a2), "l"(b2))
// duplicate one f32 into both lanes of a 64-bit pair
#define DUP2(d, s) \
    asm("mov.b64 %0, {%1, %1};" : "=l"(d) : "f"(s))

__device__ __forceinline__ float f2lo(unsigned long long v) {
    return __uint_as_float((unsigned)(v & 0xffffffffu));
}
__device__ __forceinline__ float f2hi(unsigned long long v) {
    return __uint_as_float((unsigned)(v >> 32));
}

// Grid-wide barrier: monotone counter. All NBLK blocks resident (128 <= 148 SMs).
__device__ __forceinline__ void grid_sync(unsigned base, unsigned idx) {
    __syncthreads();
    if (threadIdx.x == 0) {
        __threadfence();
        atomicAdd(&g_arrive, 1u);
        const unsigned goal = idx * (unsigned)NBLK;
        while ((*(volatile unsigned*)&g_arrive) - base < goal) { }
        __threadfence();
    }
    __syncthreads();
}

// Tiled fp32 GEMM for one 32x64 tile, 128 threads, 4x4 micro-tile computed
// with packed f32x2 FMAs. Double-buffered smem, one __syncthreads per chunk.
// Thread (mi=tid>>4, ni=tid&15) owns rows m0+mi*4+{0..3}, cols n0+ni*4+{0..3}.
__device__ __forceinline__ void gemm_acc(
    const float* __restrict__ A, const float* __restrict__ B,
    int M, int m0, int n0, float (&acc)[4][4], float* As, float* Bs)
{
    const int tid = threadIdx.x;
    const int am  = tid & 31, aj = tid >> 5;   // A loader
    const int bc  = tid & 15, bj = tid >> 4;   // B loader
    const int mi  = tid >> 4, ni = tid & 15;

    // packed accumulators: acc2[i][0] = cols {j0,j1}, acc2[i][1] = cols {j2,j3}
    unsigned long long acc2[4][2];
#pragma unroll
    for (int i = 0; i < 4; i++) { acc2[i][0] = 0ull; acc2[i][1] = 0ull; }

    const int  gm = m0 + am;
    const bool av = (gm < M);
    const float* Ap = A + gm * NN;
    const float* Bp = B + n0 + bc * 4;
    const float4 f40 = make_float4(0.f, 0.f, 0.f, 0.f);

    float4 ra0, ra1, rb0, rb1, rb2, rb3;
    ra0 = av ? *(const float4*)(Ap + aj * 4)      : f40;
    ra1 = av ? *(const float4*)(Ap + 16 + aj * 4) : f40;
    rb0 = *(const float4*)(Bp + (bj +  0) * NN);
    rb1 = *(const float4*)(Bp + (bj +  8) * NN);
    rb2 = *(const float4*)(Bp + (bj + 16) * NN);
    rb3 = *(const float4*)(Bp + (bj + 24) * NN);

    for (int c = 0; c < NCH; c++) {
        const int cb = c & 1;
        float* Aw = As + cb * (KC * 32);
        float* Bw = Bs + cb * (KC * 64);
        Aw[(aj * 4 + 0) * 32 + am] = ra0.x;
        Aw[(aj * 4 + 1) * 32 + am] = ra0.y;
        Aw[(aj * 4 + 2) * 32 + am] = ra0.z;
        Aw[(aj * 4 + 3) * 32 + am] = ra0.w;
        Aw[(16 + aj * 4 + 0) * 32 + am] = ra1.x;
        Aw[(16 + aj * 4 + 1) * 32 + am] = ra1.y;
        Aw[(16 + aj * 4 + 2) * 32 + am] = ra1.z;
        Aw[(16 + aj * 4 + 3) * 32 + am] = ra1.w;
        *(float4*)(Bw + (bj +  0) * TN + bc * 4) = rb0;
        *(float4*)(Bw + (bj +  8) * TN + bc * 4) = rb1;
        *(float4*)(Bw + (bj + 16) * TN + bc * 4) = rb2;
        *(float4*)(Bw + (bj + 24) * TN + bc * 4) = rb3;
        __syncthreads();

        const int kn = (c + 1) * KC;
        if (kn < NN) {
            ra0 = av ? *(const float4*)(Ap + kn + aj * 4)      : f40;
            ra1 = av ? *(const float4*)(Ap + kn + 16 + aj * 4) : f40;
            rb0 = *(const float4*)(Bp + (kn + bj +  0) * NN);
            rb1 = *(const float4*)(Bp + (kn + bj +  8) * NN);
            rb2 = *(const float4*)(Bp + (kn + bj + 16) * NN);
            rb3 = *(const float4*)(Bp + (kn + bj + 24) * NN);
        }

        const float*  Ab  = As + cb * (KC * 32);
        const double* Bb2 = (const double*)(Bs + cb * (KC * 64));
#pragma unroll 8
        for (int k = 0; k < KC; k++) {
            const float4  a  = *(const float4*)(Ab + k * 32 + mi * 4);
            // B cols {j0,j1},{j2,j3} already 64-bit aliased in the LDS.128 result
            const double2 bd = *(const double2*)(Bb2 + k * 32 + ni * 2);
            const unsigned long long bxy = __double_as_longlong(bd.x);
            const unsigned long long bzw = __double_as_longlong(bd.y);
            unsigned long long a0, a1, a2, a3;
            DUP2(a0, a.x); DUP2(a1, a.y); DUP2(a2, a.z); DUP2(a3, a.w);
            FFMA2(acc2[0][0], a0, bxy); FFMA2(acc2[0][1], a0, bzw);
            FFMA2(acc2[1][0], a1, bxy); FFMA2(acc2[1][1], a1, bzw);
            FFMA2(acc2[2][0], a2, bxy); FFMA2(acc2[2][1], a2, bzw);
            FFMA2(acc2[3][0], a3, bxy); FFMA2(acc2[3][1], a3, bzw);
        }
    }
    __syncthreads();

#pragma unroll
    for (int i = 0; i < 4; i++) {
        acc[i][0] = f2lo(acc2[i][0]);
        acc[i][1] = f2hi(acc2[i][0]);
        acc[i][2] = f2lo(acc2[i][1]);
        acc[i][3] = f2hi(acc2[i][1]);
    }
}

extern "C" __global__ void __launch_bounds__(NTHR, 1) rnn_kernel(
    const unsigned* __restrict__ cue,
    const float* __restrict__ ec3_last,
    const float* __restrict__ ec5_last,
    const float* __restrict__ ca1bias,
    const float* __restrict__ wca3ca1,
    const float* __restrict__ wec3ca1,
    const float* __restrict__ wca1ec5,
    const float* __restrict__ wca1act,
    const float* __restrict__ actbias,
    float* __restrict__ out)
{
    __shared__ float As[2 * KC * 32];
    __shared__ float Bs[2 * KC * 64];
    __shared__ unsigned s_base;

    const int tid = threadIdx.x;
    const int b   = blockIdx.x;

    if (tid == 0) s_base = *(volatile unsigned*)&g_arrive;
    __syncthreads();
    const unsigned base = s_base;
    unsigned bar = 0;

    // ---- phase 0: copy state, compute CA3 place fields ----
    {
        const int stride = NBLK * NTHR;
        for (int i = b * NTHR + tid; i < BSZ * NN; i += stride) {
            g_ec3[i] = ec3_last[i];
            g_ec5[i] = ec5_last[i];
        }
        for (int i = b * NTHR + tid; i < TT * NN; i += stride) {
            const int   t = i >> 10;
            const int   k = i & 1023;
            const float c = (100.0f / 1023.0f) * (float)k;   // linspace(0,100,1024)
            const float d = c - (float)t;
            g_ca3[i] = expf(-d * d * 0.02f);
        }
    }
    grid_sync(base, ++bar);

    const int m0 = (b >> 4) * TM;
    const int n0 = (b & 15) * TN;
    const int mi = tid >> 4, ni = tid & 15;

    // ---- phase 1: drive = ca3all @ wca3ca1 (100x1024x1024), blocks 0..63 ----
    if (b < 64) {
        float acc[4][4];
        gemm_acc(g_ca3, wca3ca1, TT, m0, n0, acc, As, Bs);
#pragma unroll
        for (int i = 0; i < 4; i++) {
            const int m = m0 + mi * 4 + i;
            if (m < TT) {
#pragma unroll
                for (int j = 0; j < 4; j++)
                    g_drive[m * NN + n0 + ni * 4 + j] = acc[i][j];
            }
        }
    }
    grid_sync(base, ++bar);

    // ---- recurrent scan ----
    for (int t = 0; t < TT; t++) {
        float acc[4][4];

        // GEMM1: tmp = ec3 @ wec3ca1 ; ca1 = relu(drive*(1+sigm(tmp)) - bias)
        gemm_acc(g_ec3, wec3ca1, BSZ, m0, n0, acc, As, Bs);
        const float* drow = g_drive + t * NN;
#pragma unroll
        for (int i = 0; i < 4; i++) {
            const int m = m0 + mi * 4 + i;
#pragma unroll
            for (int j = 0; j < 4; j++) {
                const int n = n0 + ni * 4 + j;
                float v = drow[n] * (1.0f + sigm(acc[i][j])) - ca1bias[n];
                v = fmaxf(v, 0.0f);
                g_ca1[m * NN + n] = v;
                if (m == 0)      out[O_C1H + t * NN + n] = v;
                if (t == TT - 1) out[O_C1F + m * NN + n] = v;
            }
        }
        grid_sync(base, ++bar);

        // GEMM2: ec5 += ca1 @ wca1ec5; squash; ec3 update + cue mask
        gemm_acc(g_ca1, wca1ec5, BSZ, m0, n0, acc, As, Bs);
#pragma unroll
        for (int i = 0; i < 4; i++) {
            const int m = m0 + mi * 4 + i;
#pragma unroll
            for (int j = 0; j < 4; j++) {
                const int n   = n0 + ni * 4 + j;
                const int idx = m * NN + n;
                float e5 = g_ec5[idx] + acc[i][j];
                e5 = 0.69f + 0.3f * sigm(4.0f * (e5 - 0.3f));
                float e3 = e5 * g_ec3[idx];
                // cueloc = 8*(s+2): t==16 -> cue[:,0,:], t==24 -> cue[:,1,:]
                if (t == 16 && cue[m * 2048 + n]        != 0u) e3 = 0.4f * e3 + 0.6f;
                if (t == 24 && cue[m * 2048 + 1024 + n] != 0u) e3 = 0.4f * e3 + 0.6f;
                g_ec5[idx] = e5;
                g_ec3[idx] = e3;
                if (m == 0) {
                    out[O_E3H + t * NN + n] = e3;
                    out[O_E5H + t * NN + n] = e5;
                }
                if (t == TT - 1) {
                    out[O_E3F + idx] = e3;
                    out[O_E5F + idx] = e5;
                }
            }
        }
        grid_sync(base, ++bar);
    }

    // ---- actCell = ca1_final @ wca1act + actbias (256x2, K=1024) ----
    {
        const int w = tid >> 5, lane = tid & 31;
        const int r = 2 * b + (w >> 1);
        const int a = w & 1;
        float s = 0.0f;
        for (int k = lane; k < NN; k += 32)
            s = fmaf(g_ca1[r * NN + k], wca1act[k * 2 + a], s);
#pragma unroll
        for (int off = 16; off; off >>= 1)
            s += __shfl_xor_sync(0xffffffffu, s, off);
        if (lane == 0) out[O_ACT + r * 2 + a] = s + actbias[a];
    }
}

extern "C" void kernel_launch(void* const* d_in, const int* in_sizes, int n_in,
                              void* d_out, int out_size)
{
    // metadata order: cue, ec3_last, ec5_last, ca1_last, ca1bias, wca3ca1,
    //                 wec3ca1, wca1ec5, wca1act, actbias
    rnn_kernel<<<NBLK, NTHR>>>(
        (const unsigned*)d_in[0],
        (const float*)d_in[1],
        (const float*)d_in[2],
        (const float*)d_in[4],
        (const float*)d_in[5],
        (const float*)d_in[6],
        (const float*)d_in[7],
        (const float*)d_in[8],
        (const float*)d_in[9],
        (float*)d_out);
}

// round 4
// speedup vs baseline: 1.1042x; 1.1042x over previous
#include <cuda_runtime.h>
#include <math.h>

// Problem constants
#define BSZ  256
#define NN   1024
#define TT   100
#define NBLK 128
#define NTHR 256
#define TM   32
#define TN   64
#define KC   32
#define KHALF 512
#define NCHG  (KHALF / KC)   // 16 chunks per warp-group

// Output layout (floats)
#define O_ACT 0
#define O_E3H 512
#define O_E5H (512 + 102400)
#define O_C1H (512 + 2*102400)
#define O_E3F (512 + 3*102400)
#define O_E5F (O_E3F + 262144)
#define O_C1F (O_E5F + 262144)

// Persistent device state
__device__ float g_ec3[BSZ*NN];
__device__ float g_ec5[BSZ*NN];
__device__ float g_ca1[BSZ*NN];
__device__ float g_ca3[TT*NN];
__device__ float g_drive[TT*NN];
__device__ unsigned g_full = 0;           // full-grid ticket counter
__device__ unsigned g_grp[8 * 32];        // per-m-group counters, 128B apart

__device__ __forceinline__ float sigm(float x) {
    return __fdividef(1.0f, 1.0f + __expf(-x));
}

// packed f32x2 FMA (FFMA2): two IEEE fp32 fmas per instruction
#define FFMA2(acc, a2, b2) \
    asm("fma.rn.f32x2 %0, %1, %2, %0;" : "+l"(acc) : "l"(a2), "l"(b2))
#define DUP2(d, s) \
    asm("mov.b64 %0, {%1, %1};" : "=l"(d) : "f"(s))

__device__ __forceinline__ float f2lo(unsigned long long v) {
    return __uint_as_float((unsigned)(v & 0xffffffffu));
}
__device__ __forceinline__ float f2hi(unsigned long long v) {
    return __uint_as_float((unsigned)(v >> 32));
}

// Ticket barrier: no base capture, race-free, wrap-safe. Counter stays a
// multiple of N after every launch (every member syncs the same # of times).
__device__ __forceinline__ void ticket_sync(unsigned* ctr, unsigned N) {
    __syncthreads();
    if (threadIdx.x == 0) {
        __threadfence();
        const unsigned r    = atomicAdd(ctr, 1u);
        const unsigned goal = (r & ~(N - 1u)) + N;
        while ((*(volatile unsigned*)ctr) - r < goal - r) { }
        __threadfence();
    }
    __syncthreads();
}
#define FULL_SYNC()      ticket_sync(&g_full, NBLK)
#define GROUP_SYNC(grp)  ticket_sync(&g_grp[(grp) << 5], 16u)

// Split-K tiled GEMM: 256 threads, 2 warp-groups, each computes the full
// 32x64 tile over half of K with FFMA2 row-pair accumulators.
// Thread wt=(tid&127): mi=wt>>4, ni=wt&15; rows m0+mi*4+{0..3}, cols n0+ni*4+{0..3}.
// acc2[ip][j] = packed rows {mi*4+2ip, mi*4+2ip+1}, col n0+ni*4+j.
__device__ __forceinline__ void gemm_split(
    const float* __restrict__ A, const float* __restrict__ B,
    int M, int m0, int n0, unsigned long long (&acc2)[2][4],
    float* As, float* Bs)
{
    const int tid = threadIdx.x;
    const int g   = tid >> 7;         // warp-group: K-half
    const int wt  = tid & 127;
    const int am  = wt & 31, aj = wt >> 5;
    const int bc  = wt & 15, bj = wt >> 4;
    const int mi  = wt >> 4, ni = wt & 15;
    const int k0  = g * KHALF;

#pragma unroll
    for (int i = 0; i < 2; i++)
#pragma unroll
        for (int j = 0; j < 4; j++) acc2[i][j] = 0ull;

    const int  gm = m0 + am;
    const bool av = (gm < M);
    const float* Ap = A + gm * NN + k0;
    const float* Bp = B + (k0 + bj) * NN + n0 + bc * 4;
    const float4 f40 = make_float4(0.f, 0.f, 0.f, 0.f);

    float* Asg = As + g * (2 * KC * 32);
    float* Bsg = Bs + g * (2 * KC * 64);

    float4 ra0, ra1, rb0, rb1, rb2, rb3;
    ra0 = av ? *(const float4*)(Ap + aj * 4)      : f40;
    ra1 = av ? *(const float4*)(Ap + 16 + aj * 4) : f40;
    rb0 = *(const float4*)(Bp);
    rb1 = *(const float4*)(Bp +  8 * NN);
    rb2 = *(const float4*)(Bp + 16 * NN);
    rb3 = *(const float4*)(Bp + 24 * NN);

    for (int c = 0; c < NCHG; c++) {
        const int cb = c & 1;
        float* Aw = Asg + cb * (KC * 32);
        float* Bw = Bsg + cb * (KC * 64);
        Aw[(aj * 4 + 0) * 32 + am] = ra0.x;
        Aw[(aj * 4 + 1) * 32 + am] = ra0.y;
        Aw[(aj * 4 + 2) * 32 + am] = ra0.z;
        Aw[(aj * 4 + 3) * 32 + am] = ra0.w;
        Aw[(16 + aj * 4 + 0) * 32 + am] = ra1.x;
        Aw[(16 + aj * 4 + 1) * 32 + am] = ra1.y;
        Aw[(16 + aj * 4 + 2) * 32 + am] = ra1.z;
        Aw[(16 + aj * 4 + 3) * 32 + am] = ra1.w;
        *(float4*)(Bw + (bj +  0) * TN + bc * 4) = rb0;
        *(float4*)(Bw + (bj +  8) * TN + bc * 4) = rb1;
        *(float4*)(Bw + (bj + 16) * TN + bc * 4) = rb2;
        *(float4*)(Bw + (bj + 24) * TN + bc * 4) = rb3;
        __syncthreads();

        if (c + 1 < NCHG) {
            const int kn = (c + 1) * KC;
            ra0 = av ? *(const float4*)(Ap + kn + aj * 4)      : f40;
            ra1 = av ? *(const float4*)(Ap + kn + 16 + aj * 4) : f40;
            rb0 = *(const float4*)(Bp + (kn +  0) * NN);
            rb1 = *(const float4*)(Bp + (kn +  8) * NN);
            rb2 = *(const float4*)(Bp + (kn + 16) * NN);
            rb3 = *(const float4*)(Bp + (kn + 24) * NN);
        }

        const float* Ab = Asg + cb * (KC * 32);
        const float* Bb = Bsg + cb * (KC * 64);
#pragma unroll 8
        for (int k = 0; k < KC; k++) {
            // A row-pairs: float4 = rows {4mi..4mi+3}; 64-bit lanes are pairs
            const double2 ad = *(const double2*)(Ab + k * 32 + mi * 4);
            const unsigned long long ap0 = __double_as_longlong(ad.x);
            const unsigned long long ap1 = __double_as_longlong(ad.y);
            const float4 b = *(const float4*)(Bb + k * 64 + ni * 4);
            unsigned long long b0, b1, b2, b3;
            DUP2(b0, b.x); DUP2(b1, b.y); DUP2(b2, b.z); DUP2(b3, b.w);
            FFMA2(acc2[0][0], ap0, b0); FFMA2(acc2[1][0], ap1, b0);
            FFMA2(acc2[0][1], ap0, b1); FFMA2(acc2[1][1], ap1, b1);
            FFMA2(acc2[0][2], ap0, b2); FFMA2(acc2[1][2], ap1, b2);
            FFMA2(acc2[0][3], ap0, b3); FFMA2(acc2[1][3], ap1, b3);
        }
    }
}

// Cross-group reduction: both halves' partials summed; thread o=tid handles
// rows m0 + mi2*4 + half*2 + {0,1}, cols n0 + ni2*4 + {0..3}.
//   half = tid>>7, r_lo = tid&127, mi2 = r_lo>>4, ni2 = r_lo&15
__device__ __forceinline__ void reduce_vals(
    const unsigned long long (&acc2)[2][4], float (&vals)[2][4], float* smem)
{
    unsigned long long* red = (unsigned long long*)smem;  // 256*8 u64 = 16KB
    const int tid = threadIdx.x;
    __syncthreads();   // all mainloop smem reads done before aliasing overwrite
#pragma unroll
    for (int i = 0; i < 2; i++)
#pragma unroll
        for (int j = 0; j < 4; j++)
            red[(tid << 3) + i * 4 + j] = acc2[i][j];
    __syncthreads();
    const int half = tid >> 7, r_lo = tid & 127;
#pragma unroll
    for (int j = 0; j < 4; j++) {
        const unsigned long long p0 = red[(r_lo << 3) + half * 4 + j];
        const unsigned long long p1 = red[((128 + r_lo) << 3) + half * 4 + j];
        vals[0][j] = f2lo(p0) + f2lo(p1);
        vals[1][j] = f2hi(p0) + f2hi(p1);
    }
}

extern "C" __global__ void __launch_bounds__(NTHR, 1) rnn_kernel(
    const unsigned* __restrict__ cue,
    const float* __restrict__ ec3_last,
    const float* __restrict__ ec5_last,
    const float* __restrict__ ca1bias,
    const float* __restrict__ wca3ca1,
    const float* __restrict__ wec3ca1,
    const float* __restrict__ wca1ec5,
    const float* __restrict__ wca1act,
    const float* __restrict__ actbias,
    float* __restrict__ out)
{
    __shared__ float As[2 * 2 * KC * 32];   // 16 KB
    __shared__ float Bs[2 * 2 * KC * 64];   // 32 KB (reduction buffer aliases this)

    const int tid = threadIdx.x;
    const int b   = blockIdx.x;
    const int grp = b >> 4;                 // m-group (shares rows m0..m0+31)

    // ---- phase 0: copy state, compute CA3 place fields ----
    {
        const int stride = NBLK * NTHR;
        for (int i = b * NTHR + tid; i < BSZ * NN; i += stride) {
            g_ec3[i] = ec3_last[i];
            g_ec5[i] = ec5_last[i];
        }
        for (int i = b * NTHR + tid; i < TT * NN; i += stride) {
            const int   t = i >> 10;
            const int   k = i & 1023;
            const float c = (100.0f / 1023.0f) * (float)k;   // linspace(0,100,1024)
            const float d = c - (float)t;
            g_ca3[i] = expf(-d * d * 0.02f);
        }
    }
    FULL_SYNC();

    const int m0   = grp * TM;
    const int n0   = (b & 15) * TN;
    const int half = tid >> 7, r_lo = tid & 127;
    const int mi2  = r_lo >> 4, ni2 = r_lo & 15;
    const int rb0_ = m0 + mi2 * 4 + half * 2;   // first of this thread's 2 rows
    const int cb0_ = n0 + ni2 * 4;

    // ---- phase 1: drive = ca3all @ wca3ca1 (100x1024), blocks 0..63 ----
    if (b < 64) {
        unsigned long long acc2[2][4];
        float vals[2][4];
        gemm_split(g_ca3, wca3ca1, TT, m0, n0, acc2, As, Bs);
        reduce_vals(acc2, vals, Bs);
#pragma unroll
        for (int i = 0; i < 2; i++) {
            const int m = rb0_ + i;
            if (m < TT) {
#pragma unroll
                for (int j = 0; j < 4; j++)
                    g_drive[m * NN + cb0_ + j] = vals[i][j];
            }
        }
    }
    FULL_SYNC();

    // ---- recurrent scan: only the 16 blocks sharing rows m0..m0+31 sync ----
    for (int t = 0; t < TT; t++) {
        unsigned long long acc2[2][4];
        float vals[2][4];

        // GEMM1: tmp = ec3 @ wec3ca1 ; ca1 = relu(drive*(1+sigm(tmp)) - bias)
        gemm_split(g_ec3, wec3ca1, BSZ, m0, n0, acc2, As, Bs);
        reduce_vals(acc2, vals, Bs);
        const float* drow = g_drive + t * NN;
#pragma unroll
        for (int i = 0; i < 2; i++) {
            const int m = rb0_ + i;
#pragma unroll
            for (int j = 0; j < 4; j++) {
                const int n = cb0_ + j;
                float v = drow[n] * (1.0f + sigm(vals[i][j])) - ca1bias[n];
                v = fmaxf(v, 0.0f);
                g_ca1[m * NN + n] = v;
                if (m == 0)      out[O_C1H + t * NN + n] = v;
                if (t == TT - 1) out[O_C1F + m * NN + n] = v;
            }
        }
        GROUP_SYNC(grp);

        // GEMM2: ec5 += ca1 @ wca1ec5; squash; ec3 update + cue mask
        gemm_split(g_ca1, wca1ec5, BSZ, m0, n0, acc2, As, Bs);
        reduce_vals(acc2, vals, Bs);
#pragma unroll
        for (int i = 0; i < 2; i++) {
            const int m = rb0_ + i;
#pragma unroll
            for (int j = 0; j < 4; j++) {
                const int n   = cb0_ + j;
                const int idx = m * NN + n;
                float e5 = g_ec5[idx] + vals[i][j];
                e5 = 0.69f + 0.3f * sigm(4.0f * (e5 - 0.3f));
                float e3 = e5 * g_ec3[idx];
                // cueloc = 8*(s+2): t==16 -> cue[:,0,:], t==24 -> cue[:,1,:]
                if (t == 16 && cue[m * 2048 + n]        != 0u) e3 = 0.4f * e3 + 0.6f;
                if (t == 24 && cue[m * 2048 + 1024 + n] != 0u) e3 = 0.4f * e3 + 0.6f;
                g_ec5[idx] = e5;
                g_ec3[idx] = e3;
                if (m == 0) {
                    out[O_E3H + t * NN + n] = e3;
                    out[O_E5H + t * NN + n] = e5;
                }
                if (t == TT - 1) {
                    out[O_E3F + idx] = e3;
                    out[O_E5F + idx] = e5;
                }
            }
        }
        GROUP_SYNC(grp);
    }

    // ---- actCell = ca1_final @ wca1act + actbias (rows 2b, 2b+1) ----
    {
        const int w = tid >> 5, lane = tid & 31;
        if (w < 4) {
            const int r = 2 * b + (w >> 1);
            const int a = w & 1;
            float s = 0.0f;
            for (int k = lane; k < NN; k += 32)
                s = fmaf(g_ca1[r * NN + k], wca1act[k * 2 + a], s);
#pragma unroll
            for (int off = 16; off; off >>= 1)
                s += __shfl_xor_sync(0xffffffffu, s, off);
            if (lane == 0) out[O_ACT + r * 2 + a] = s + actbias[a];
        }
    }
}

extern "C" void kernel_launch(void* const* d_in, const int* in_sizes, int n_in,
                              void* d_out, int out_size)
{
    // metadata order: cue, ec3_last, ec5_last, ca1_last, ca1bias, wca3ca1,
    //                 wec3ca1, wca1ec5, wca1act, actbias
    rnn_kernel<<<NBLK, NTHR>>>(
        (const unsigned*)d_in[0],
        (const float*)d_in[1],
        (const float*)d_in[2],
        (const float*)d_in[4],
        (const float*)d_in[5],
        (const float*)d_in[6],
        (const float*)d_in[7],
        (const float*)d_in[8],
        (const float*)d_in[9],
        (float*)d_out);
}

// round 7
// speedup vs baseline: 2.0246x; 1.8336x over previous
#include <cuda_runtime.h>
#include <cuda_bf16.h>
#include <math.h>

#define BSZ  256
#define NN   1024
#define TT   100
#define NBLK 128
#define NTHR 256
#define TM   32
#define TN   64
#define KC   64
#define NCH  16
#define STAGE_BYTES 24576   // Ah 4K | Al 4K | Bh 8K | Bl 8K
#define SMEM_TOTAL  (2 * STAGE_BYTES)   // 49152 = default limit, no attribute call

// Output layout (floats)
#define O_ACT 0
#define O_E3H 512
#define O_E5H (512 + 102400)
#define O_C1H (512 + 2*102400)
#define O_E3F (512 + 3*102400)
#define O_E5F (O_E3F + 262144)
#define O_C1F (O_E5F + 262144)

// ---- persistent device state ----
__device__ float g_ec5[BSZ*NN];
__device__ float g_ec3[BSZ*NN];
__device__ float g_ca1[BSZ*NN];
__device__ float g_drive[TT*NN];
__device__ __align__(16) __nv_bfloat16 g_ec3h[BSZ*NN], g_ec3l[BSZ*NN];
__device__ __align__(16) __nv_bfloat16 g_ca1h[BSZ*NN], g_ca1l[BSZ*NN];
__device__ __align__(16) __nv_bfloat16 g_ca3h[128*NN], g_ca3l[128*NN];
__device__ __align__(16) __nv_bfloat16 g_w0h[NN*NN], g_w0l[NN*NN];  // wca3ca1 [k][n]
__device__ __align__(16) __nv_bfloat16 g_w1h[NN*NN], g_w1l[NN*NN];  // wec3ca1 [k][n]
__device__ __align__(16) __nv_bfloat16 g_w2h[NN*NN], g_w2l[NN*NN];  // wca1ec5 [k][n]
__device__ unsigned g_full = 0;
__device__ unsigned g_grp[8 * 32];

__device__ __forceinline__ float sigm(float x) {
    return __fdividef(1.0f, 1.0f + __expf(-x));
}
__device__ __forceinline__ unsigned smem_u32(const void* p) {
    unsigned a;
    asm("{ .reg .u64 t; cvta.to.shared.u64 t, %1; cvt.u32.u64 %0, t; }" : "=r"(a) : "l"(p));
    return a;
}
#define SWZ128(o) ((unsigned)(o) ^ ((((unsigned)(o)) >> 3) & 0x70u))

__device__ __forceinline__ void ldm_a(unsigned (&r)[4], unsigned a) {
    asm volatile("ldmatrix.sync.aligned.m8n8.x4.shared.b16 {%0,%1,%2,%3}, [%4];"
        : "=r"(r[0]), "=r"(r[1]), "=r"(r[2]), "=r"(r[3]) : "r"(a));
}
__device__ __forceinline__ void ldm_bt(unsigned (&r)[4], unsigned a) {
    asm volatile("ldmatrix.sync.aligned.m8n8.x4.trans.shared.b16 {%0,%1,%2,%3}, [%4];"
        : "=r"(r[0]), "=r"(r[1]), "=r"(r[2]), "=r"(r[3]) : "r"(a));
}
__device__ __forceinline__ void mma16816(float (&d)[4], const unsigned (&a)[4],
                                         unsigned b0, unsigned b1) {
    asm volatile(
        "mma.sync.aligned.m16n8k16.row.col.f32.bf16.bf16.f32 "
        "{%0,%1,%2,%3}, {%4,%5,%6,%7}, {%8,%9}, {%0,%1,%2,%3};"
        : "+f"(d[0]), "+f"(d[1]), "+f"(d[2]), "+f"(d[3])
        : "r"(a[0]), "r"(a[1]), "r"(a[2]), "r"(a[3]), "r"(b0), "r"(b1));
}

// Ticket barrier (race-free, wrap-safe; N power of 2)
__device__ __forceinline__ void ticket_sync(unsigned* ctr, unsigned N) {
    __syncthreads();
    if (threadIdx.x == 0) {
        __threadfence();
        const unsigned r    = atomicAdd(ctr, 1u);
        const unsigned goal = (r & ~(N - 1u)) + N;
        while ((*(volatile unsigned*)ctr) - r < goal - r) { }
        __threadfence();
    }
    __syncthreads();
}
#define FULL_SYNC()    ticket_sync(&g_full, NBLK)
#define GROUP_SYNC(g)  ticket_sync(&g_grp[(g) << 5], 16u)

// bf16-split HMMA GEMM for one 32x64 tile over K=1024.
// A: [rows][k] bf16 hi/lo (pre-offset to m0). B: [k][n] bf16 hi/lo weights.
// 8 warps: wm = warp>>2 (m16), wn = warp&3 (n16). Accums d0 (n8 blk0), d1 (blk1).
__device__ __forceinline__ void gemm_mma(
    const __nv_bfloat16* __restrict__ Ah, const __nv_bfloat16* __restrict__ Al,
    const __nv_bfloat16* __restrict__ Bh, const __nv_bfloat16* __restrict__ Bl,
    int n0, char* sm, unsigned smb, float (&d0)[4], float (&d1)[4])
{
    const int tid  = threadIdx.x;
    const int warp = tid >> 5, lane = tid & 31;
    const int wm   = warp >> 2, wn = warp & 3;
    const int sel  = lane >> 3, r8 = lane & 7;

#pragma unroll
    for (int i = 0; i < 4; i++) { d0[i] = 0.f; d1[i] = 0.f; }

    // loaders: A 32 rows x 8 quads (1/thread); B 64 rows x 8 quads (2/thread)
    const int alr = tid >> 3, alq = tid & 7;
    const unsigned aso  = SWZ128(alr * 128 + alq * 16);
    const unsigned bso1 = SWZ128(alr * 128 + alq * 16);
    const unsigned bso2 = SWZ128((32 + alr) * 128 + alq * 16);

    const __nv_bfloat16* Agh  = Ah + alr * NN + alq * 8;
    const __nv_bfloat16* Agl  = Al + alr * NN + alq * 8;
    const __nv_bfloat16* Bg1h = Bh + alr * NN + n0 + alq * 8;
    const __nv_bfloat16* Bg2h = Bh + (32 + alr) * NN + n0 + alq * 8;
    const __nv_bfloat16* Bg1l = Bl + alr * NN + n0 + alq * 8;
    const __nv_bfloat16* Bg2l = Bl + (32 + alr) * NN + n0 + alq * 8;

    // ldmatrix lane addressing (tile-local byte offsets, swizzled per use)
    const unsigned a_rowoff  = (unsigned)((wm * 16 + ((sel & 1) << 3) + r8) * 128
                                          + ((sel >> 1) << 4));
    const unsigned b_rowbase = (unsigned)((((sel & 1) << 3) + r8) * 128);
    const unsigned b_colpart = (unsigned)((wn << 5) + ((sel >> 1) << 4));

    uint4 pa   = *(const uint4*)(Agh);
    uint4 pal  = *(const uint4*)(Agl);
    uint4 pb1h = *(const uint4*)(Bg1h);
    uint4 pb2h = *(const uint4*)(Bg2h);
    uint4 pb1l = *(const uint4*)(Bg1l);
    uint4 pb2l = *(const uint4*)(Bg2l);

    for (int c = 0; c < NCH; c++) {
        char* sp = sm + (c & 1) * STAGE_BYTES;
        *(uint4*)(sp + aso)          = pa;
        *(uint4*)(sp + 4096 + aso)   = pal;
        *(uint4*)(sp + 8192 + bso1)  = pb1h;
        *(uint4*)(sp + 8192 + bso2)  = pb2h;
        *(uint4*)(sp + 16384 + bso1) = pb1l;
        *(uint4*)(sp + 16384 + bso2) = pb2l;
        __syncthreads();

        if (c + 1 < NCH) {
            const int ke = (c + 1) * KC;          // element offset along k
            pa   = *(const uint4*)(Agh + ke);
            pal  = *(const uint4*)(Agl + ke);
            pb1h = *(const uint4*)(Bg1h + ke * NN);
            pb2h = *(const uint4*)(Bg2h + ke * NN);
            pb1l = *(const uint4*)(Bg1l + ke * NN);
            pb2l = *(const uint4*)(Bg2l + ke * NN);
        }

        const unsigned ab = smb + (c & 1) * STAGE_BYTES;
#pragma unroll
        for (int ks = 0; ks < 4; ks++) {
            unsigned ah[4], al4[4], bh[4], bl[4];
            const unsigned ao = ab + SWZ128(a_rowoff + ks * 32);
            ldm_a(ah, ao);
            ldm_a(al4, ao + 4096);
            const unsigned bo = ab + 8192 + SWZ128(b_rowbase + ks * 2048 + b_colpart);
            ldm_bt(bh, bo);
            ldm_bt(bl, bo + 8192);
            mma16816(d0, ah, bh[0], bh[1]);  mma16816(d1, ah, bh[2], bh[3]);
            mma16816(d0, ah, bl[0], bl[1]);  mma16816(d1, ah, bl[2], bl[3]);
            mma16816(d0, al4, bh[0], bh[1]); mma16816(d1, al4, bh[2], bh[3]);
        }
        // buffer (c&1)^1 is next overwritten only after the sync of iter c+1;
        // across gemm calls the callers' GROUP/FULL_SYNC provides the barrier.
    }
}

extern "C" __global__ void __launch_bounds__(NTHR, 1) rnn_kernel(
    const unsigned* __restrict__ cue,
    const float* __restrict__ ec3_last,
    const float* __restrict__ ec5_last,
    const float* __restrict__ ca1bias,
    const float* __restrict__ wca3ca1,
    const float* __restrict__ wec3ca1,
    const float* __restrict__ wca1ec5,
    const float* __restrict__ wca1act,
    const float* __restrict__ actbias,
    float* __restrict__ out)
{
    extern __shared__ char sm[];
    const unsigned smb = smem_u32(sm);

    const int tid  = threadIdx.x;
    const int b    = blockIdx.x;
    const int warp = tid >> 5, lane = tid & 31;
    const int wm   = warp >> 2, wn = warp & 3;
    const int tr   = lane >> 2, tc = (lane & 3) * 2;
    const int grp  = b >> 4;
    const int m0   = grp * TM;
    const int n0   = (b & 15) * TN;

    // ---- phase 0: state copy+split, ca3 split, weight split (no transpose) ----
    {
        const int gs = NBLK * NTHR;
        for (int i = b * NTHR + tid; i < BSZ * NN; i += gs) {
            const float e3 = ec3_last[i], e5 = ec5_last[i];
            g_ec3[i] = e3; g_ec5[i] = e5;
            const __nv_bfloat16 h = __float2bfloat16_rn(e3);
            g_ec3h[i] = h;
            g_ec3l[i] = __float2bfloat16_rn(e3 - __bfloat162float(h));
        }
        for (int i = b * NTHR + tid; i < 128 * NN; i += gs) {
            const int trow = i >> 10, k = i & 1023;
            float v = 0.0f;
            if (trow < TT) {
                const float c = (100.0f / 1023.0f) * (float)k;   // linspace(0,100,1024)
                const float d = c - (float)trow;
                v = expf(-d * d * 0.02f);
            }
            const __nv_bfloat16 h = __float2bfloat16_rn(v);
            g_ca3h[i] = h;
            g_ca3l[i] = __float2bfloat16_rn(v - __bfloat162float(h));
        }
        for (int i = b * NTHR + tid; i < NN * NN; i += gs) {
            const float v0 = wca3ca1[i];
            const float v1 = wec3ca1[i];
            const float v2 = wca1ec5[i];
            const __nv_bfloat16 h0 = __float2bfloat16_rn(v0);
            const __nv_bfloat16 h1 = __float2bfloat16_rn(v1);
            const __nv_bfloat16 h2 = __float2bfloat16_rn(v2);
            g_w0h[i] = h0; g_w0l[i] = __float2bfloat16_rn(v0 - __bfloat162float(h0));
            g_w1h[i] = h1; g_w1l[i] = __float2bfloat16_rn(v1 - __bfloat162float(h1));
            g_w2h[i] = h2; g_w2l[i] = __float2bfloat16_rn(v2 - __bfloat162float(h2));
        }
    }
    FULL_SYNC();

    // ---- GEMM0: drive = ca3all @ wca3ca1 (M=100 padded to 128), CTAs 0..63 ----
    if (b < 64) {
        const int m0g = (b >> 4) * TM;
        const int n0g = (b & 15) * TN;
        float d0[4], d1[4];
        gemm_mma(g_ca3h + m0g * NN, g_ca3l + m0g * NN, g_w0h, g_w0l,
                 n0g, sm, smb, d0, d1);
#pragma unroll
        for (int nb = 0; nb < 2; nb++) {
            const float* dd = nb ? d1 : d0;
#pragma unroll
            for (int e = 0; e < 4; e++) {
                const int m = m0g + wm * 16 + tr + ((e >> 1) << 3);
                const int n = n0g + wn * 16 + (nb << 3) + tc + (e & 1);
                if (m < TT) g_drive[m * NN + n] = dd[e];
            }
        }
    }
    FULL_SYNC();

    // ---- recurrent scan: 8 independent groups of 16 CTAs ----
    for (int t = 0; t < TT; t++) {
        float d0[4], d1[4];

        // GEMM1: ca1 = relu(drive_t * (1+sigm(ec3@W1)) - bias)
        gemm_mma(g_ec3h + m0 * NN, g_ec3l + m0 * NN, g_w1h, g_w1l,
                 n0, sm, smb, d0, d1);
#pragma unroll
        for (int nb = 0; nb < 2; nb++) {
            const float* dd = nb ? d1 : d0;
#pragma unroll
            for (int e = 0; e < 4; e++) {
                const int m = m0 + wm * 16 + tr + ((e >> 1) << 3);
                const int n = n0 + wn * 16 + (nb << 3) + tc + (e & 1);
                const int idx = m * NN + n;
                float v = g_drive[t * NN + n] * (1.0f + sigm(dd[e])) - ca1bias[n];
                v = fmaxf(v, 0.0f);
                g_ca1[idx] = v;
                const __nv_bfloat16 h = __float2bfloat16_rn(v);
                g_ca1h[idx] = h;
                g_ca1l[idx] = __float2bfloat16_rn(v - __bfloat162float(h));
                if (m == 0)      out[O_C1H + t * NN + n] = v;
                if (t == TT - 1) out[O_C1F + idx] = v;
            }
        }
        GROUP_SYNC(grp);

        // GEMM2: ec5' = squash(ec5 + ca1@W2); ec3' = ec5'*ec3 (+ cue mask)
        gemm_mma(g_ca1h + m0 * NN, g_ca1l + m0 * NN, g_w2h, g_w2l,
                 n0, sm, smb, d0, d1);
#pragma unroll
        for (int nb = 0; nb < 2; nb++) {
            const float* dd = nb ? d1 : d0;
#pragma unroll
            for (int e = 0; e < 4; e++) {
                const int m = m0 + wm * 16 + tr + ((e >> 1) << 3);
                const int n = n0 + wn * 16 + (nb << 3) + tc + (e & 1);
                const int idx = m * NN + n;
                float e5 = g_ec5[idx] + dd[e];
                e5 = 0.69f + 0.3f * sigm(4.0f * (e5 - 0.3f));
                float e3 = e5 * g_ec3[idx];
                // cueloc = 8*(s+2): t==16 -> cue[:,0,:], t==24 -> cue[:,1,:]
                if (t == 16 && cue[m * 2048 + n]        != 0u) e3 = 0.4f * e3 + 0.6f;
                if (t == 24 && cue[m * 2048 + 1024 + n] != 0u) e3 = 0.4f * e3 + 0.6f;
                g_ec5[idx] = e5;
                g_ec3[idx] = e3;
                const __nv_bfloat16 h = __float2bfloat16_rn(e3);
                g_ec3h[idx] = h;
                g_ec3l[idx] = __float2bfloat16_rn(e3 - __bfloat162float(h));
                if (m == 0) {
                    out[O_E3H + t * NN + n] = e3;
                    out[O_E5H + t * NN + n] = e5;
                }
                if (t == TT - 1) {
                    out[O_E3F + idx] = e3;
                    out[O_E5F + idx] = e5;
                }
            }
        }
        GROUP_SYNC(grp);
    }

    // ---- actCell = ca1_final @ wca1act + actbias (rows 2b, 2b+1) ----
    {
        if (warp < 4) {
            const int r = 2 * b + (warp >> 1);
            const int a = warp & 1;
            float s = 0.0f;
            for (int k = lane; k < NN; k += 32)
                s = fmaf(g_ca1[r * NN + k], wca1act[k * 2 + a], s);
#pragma unroll
            for (int off = 16; off; off >>= 1)
                s += __shfl_xor_sync(0xffffffffu, s, off);
            if (lane == 0) out[O_ACT + r * 2 + a] = s + actbias[a];
        }
    }
}

extern "C" void kernel_launch(void* const* d_in, const int* in_sizes, int n_in,
                              void* d_out, int out_size)
{
    // metadata order: cue, ec3_last, ec5_last, ca1_last, ca1bias, wca3ca1,
    //                 wec3ca1, wca1ec5, wca1act, actbias
    rnn_kernel<<<NBLK, NTHR, SMEM_TOTAL>>>(
        (const unsigned*)d_in[0],
        (const float*)d_in[1],
        (const float*)d_in[2],
        (const float*)d_in[4],
        (const float*)d_in[5],
        (const float*)d_in[6],
        (const float*)d_in[7],
        (const float*)d_in[8],
        (const float*)d_in[9],
        (float*)d_out);
}